// round 1
// baseline (speedup 1.0000x reference)
#include <cuda_runtime.h>
#include <cuda_fp16.h>

#define DIN    8192
#define DOUT   8192
#define MROWS  32
#define KSPLIT 16
#define KRANGE (DIN / KSPLIT)   // 512
#define KC     128              // k-chunk staged through smem
#define NTILE  512              // n columns per CTA
#define THREADS 128

typedef unsigned long long u64;

// Scratch (static device globals — no runtime allocation).
__device__ float2 g_xp[DIN * (MROWS / 2)];            // x packed as [k][m-pair]  (1 MB)
__device__ float  g_partial[KSPLIT * MROWS * DOUT];   // split-k partials        (16 MB)

__device__ __forceinline__ u64 fma2(u64 a, u64 b, u64 c) {
    u64 d;
    asm("fma.rn.f32x2 %0, %1, %2, %3;" : "=l"(d) : "l"(a), "l"(b), "l"(c));
    return d;
}
__device__ __forceinline__ u64 pack2(float v) {
    u64 r;
    asm("mov.b64 %0, {%1, %1};" : "=l"(r) : "f"(v));
    return r;
}
__device__ __forceinline__ void unpack2(u64 v, float& lo, float& hi) {
    asm("mov.b64 {%0, %1}, %2;" : "=f"(lo), "=f"(hi) : "l"(v));
}

// ---------------------------------------------------------------------------
// Prolog: transpose/pack x[32][8192] -> g_xp[k][p] = (x[2p][k], x[2p+1][k])
// ---------------------------------------------------------------------------
__global__ void prep_x_kernel(const float* __restrict__ x) {
    int k = blockIdx.x * blockDim.x + threadIdx.x;
    if (k >= DIN) return;
#pragma unroll
    for (int p = 0; p < MROWS / 2; p++) {
        float2 v;
        v.x = x[(size_t)(2 * p)     * DIN + k];   // coalesced across warp in k
        v.y = x[(size_t)(2 * p + 1) * DIN + k];
        g_xp[(size_t)k * (MROWS / 2) + p] = v;    // contiguous per thread
    }
}

// ---------------------------------------------------------------------------
// Main: fused Q4_0 fake-dequant + GEMM partial.
// grid = (DOUT/NTILE, KSPLIT). Each thread owns 4 consecutive n-columns;
// a 32-wide quant block spans 8 lanes -> butterfly-shuffle abs-argmax.
// ---------------------------------------------------------------------------
__global__ void __launch_bounds__(THREADS, 2)
gemm_kernel(const float* __restrict__ W) {
    __shared__ float2 xs[KC * (MROWS / 2)];   // 16 KB

    const int tid  = threadIdx.x;
    const int lane = tid & 31;
    const int n0   = blockIdx.x * NTILE + tid * 4;
    const int k0   = blockIdx.y * KRANGE;

    u64 acc[4][16];
#pragma unroll
    for (int c = 0; c < 4; c++)
#pragma unroll
        for (int p = 0; p < 16; p++) acc[c][p] = 0ull;

    const float4* Wp = reinterpret_cast<const float4*>(W)
                     + (size_t)k0 * (DOUT / 4) + (n0 >> 2);

    float4 wnext = Wp[0];   // software prefetch, distance 1

    for (int kc = 0; kc < KRANGE; kc += KC) {
        __syncthreads();
        {   // stage x chunk: KC*16 float2 = 1024 float4
            const float4* src = reinterpret_cast<const float4*>(
                g_xp + (size_t)(k0 + kc) * (MROWS / 2));
            float4* dst = reinterpret_cast<float4*>(xs);
#pragma unroll
            for (int i = 0; i < 8; i++)
                dst[tid + i * THREADS] = src[tid + i * THREADS];
        }
        __syncthreads();

#pragma unroll 1
        for (int kk = 0; kk < KC; kk++) {
            float4 w = wnext;
            int knext = kc + kk + 1;
            if (knext < KRANGE)
                wnext = Wp[(size_t)knext * (DOUT / 4)];

            // ---- abs-argmax (signed value) over the 32-wide block ----
            float b = w.x;
            if (fabsf(w.y) > fabsf(b)) b = w.y;   // strict > keeps earliest index
            if (fabsf(w.z) > fabsf(b)) b = w.z;
            if (fabsf(w.w) > fabsf(b)) b = w.w;
#pragma unroll
            for (int off = 1; off <= 4; off <<= 1) {
                float o  = __shfl_xor_sync(0xffffffffu, b, off);
                float ab = fabsf(b), ao = fabsf(o);
                bool keep = (ab > ao) || (ab == ao && (lane & off) == 0);
                b = keep ? b : o;
            }

            // ---- Q4_0 scale (fp16 round-trip) + RN reciprocal ----
            float d     = b * -0.125f;                       // exact: /8
            float scale = __half2float(__float2half_rn(d));  // fp16 round-trip
            float inv   = __frcp_rn(d);                      // == RN(1/d) == 1.0/d
            float n8s   = scale * -8.0f;

            // ---- dequant 4 weights ----
            float wv[4] = {w.x, w.y, w.z, w.w};
            u64 wb[4];
#pragma unroll
            for (int c = 0; c < 4; c++) {
                float t = fmaf(wv[c], inv, 8.5f);  // in [~0.5, ~16.5]; NaN if zero-block
                t = truncf(t);
                t = fminf(t, 15.0f);               // fminf(NaN,15)=15 -> scale(=0)*7=0
                wb[c] = pack2(fmaf(scale, t, n8s)); // scale*(q-8), exact
            }

            // ---- 64 packed f32x2 FMAs: 4 cols x 16 m-pairs ----
            const u64* xk = reinterpret_cast<const u64*>(xs + kk * (MROWS / 2));
#pragma unroll
            for (int p = 0; p < 16; p++) {
                u64 xv = xk[p];                     // broadcast LDS.64
                acc[0][p] = fma2(xv, wb[0], acc[0][p]);
                acc[1][p] = fma2(xv, wb[1], acc[1][p]);
                acc[2][p] = fma2(xv, wb[2], acc[2][p]);
                acc[3][p] = fma2(xv, wb[3], acc[3][p]);
            }
        }
    }

    // ---- write split-k partials (coalesced float4 rows) ----
    float* out = g_partial + (size_t)blockIdx.y * (MROWS * DOUT);
#pragma unroll
    for (int p = 0; p < 16; p++) {
        float lo0, hi0, lo1, hi1, lo2, hi2, lo3, hi3;
        unpack2(acc[0][p], lo0, hi0);
        unpack2(acc[1][p], lo1, hi1);
        unpack2(acc[2][p], lo2, hi2);
        unpack2(acc[3][p], lo3, hi3);
        *reinterpret_cast<float4*>(out + (size_t)(2 * p)     * DOUT + n0) =
            make_float4(lo0, lo1, lo2, lo3);
        *reinterpret_cast<float4*>(out + (size_t)(2 * p + 1) * DOUT + n0) =
            make_float4(hi0, hi1, hi2, hi3);
    }
}

// ---------------------------------------------------------------------------
// Epilog: out = bias + sum_k partials
// ---------------------------------------------------------------------------
__global__ void reduce_kernel(const float* __restrict__ bias, float* __restrict__ out) {
    int i = blockIdx.x * blockDim.x + threadIdx.x;   // float4 index
    if (i >= (MROWS * DOUT) / 4) return;
    int n4 = i & (DOUT / 4 - 1);
    float4 s = reinterpret_cast<const float4*>(bias)[n4];
#pragma unroll
    for (int ks = 0; ks < KSPLIT; ks++) {
        float4 p = reinterpret_cast<const float4*>(
            g_partial + (size_t)ks * MROWS * DOUT)[i];
        s.x += p.x; s.y += p.y; s.z += p.z; s.w += p.w;
    }
    reinterpret_cast<float4*>(out)[i] = s;
}

// ---------------------------------------------------------------------------
extern "C" void kernel_launch(void* const* d_in, const int* in_sizes, int n_in,
                              void* d_out, int out_size) {
    const float *X = nullptr, *W = nullptr, *B = nullptr;
    for (int i = 0; i < n_in; i++) {
        long long sz = in_sizes[i];
        if (sz == (long long)DIN * DOUT)      W = (const float*)d_in[i];
        else if (sz == (long long)MROWS*DIN)  X = (const float*)d_in[i];
        else if (sz == (long long)DOUT)       B = (const float*)d_in[i];
    }

    prep_x_kernel<<<DIN / 256, 256>>>(X);

    dim3 grid(DOUT / NTILE, KSPLIT);
    gemm_kernel<<<grid, THREADS>>>(W);

    reduce_kernel<<<(MROWS * DOUT / 4 + 255) / 256, 256>>>(B, (float*)d_out);
}

// round 3
// speedup vs baseline: 1.9460x; 1.9460x over previous
#include <cuda_runtime.h>
#include <cuda_fp16.h>

#define DIN    8192
#define DOUT   8192
#define MROWS  32
#define KSPLIT 16
#define KRANGE (DIN / KSPLIT)   // 512
#define KC     128              // k-chunk staged through smem
#define KU     4                // k unroll / W prefetch depth (MLP)
#define NTILE  512              // n columns per CTA
#define THREADS 128

typedef unsigned long long u64;

// Scratch (static device globals — no runtime allocation).
__device__ float2 g_xp[DIN * (MROWS / 2)];            // x packed as [k][m-pair]  (1 MB)
__device__ float  g_partial[KSPLIT * MROWS * DOUT];   // split-k partials        (16 MB)

__device__ __forceinline__ u64 fma2(u64 a, u64 b, u64 c) {
    u64 d;
    asm("fma.rn.f32x2 %0, %1, %2, %3;" : "=l"(d) : "l"(a), "l"(b), "l"(c));
    return d;
}
__device__ __forceinline__ u64 pack2(float v) {
    u64 r;
    asm("mov.b64 %0, {%1, %1};" : "=l"(r) : "f"(v));
    return r;
}
__device__ __forceinline__ void unpack2(u64 v, float& lo, float& hi) {
    asm("mov.b64 {%0, %1}, %2;" : "=f"(lo), "=f"(hi) : "l"(v));
}

// ---------------------------------------------------------------------------
// Prolog: transpose/pack x[32][8192] -> g_xp[k][p] = (x[2p][k], x[2p+1][k])
// ---------------------------------------------------------------------------
__global__ void prep_x_kernel(const float* __restrict__ x) {
    int k = blockIdx.x * blockDim.x + threadIdx.x;
    if (k >= DIN) return;
#pragma unroll
    for (int p = 0; p < MROWS / 2; p++) {
        float2 v;
        v.x = x[(size_t)(2 * p)     * DIN + k];   // coalesced across warp in k
        v.y = x[(size_t)(2 * p + 1) * DIN + k];
        g_xp[(size_t)k * (MROWS / 2) + p] = v;    // contiguous per thread
    }
}

// ---------------------------------------------------------------------------
// Main: fused Q4_0 fake-dequant + GEMM partial.
// grid = (DOUT/NTILE, KSPLIT). Each thread owns 4 consecutive n-columns;
// a 32-wide quant block spans 8 lanes -> butterfly-shuffle abs-argmax.
// k-loop unrolled by KU=4 with front-batched W prefetch (MLP=4) so the
// 577-cycle DRAM latency is covered by ~880 issue-cycles per SMSP per group.
// ---------------------------------------------------------------------------
__global__ void __launch_bounds__(THREADS, 2)
gemm_kernel(const float* __restrict__ W) {
    __shared__ float2 xs[KC * (MROWS / 2)];   // 16 KB

    const int tid  = threadIdx.x;
    const int lane = tid & 31;
    const int n0   = blockIdx.x * NTILE + tid * 4;
    const int k0   = blockIdx.y * KRANGE;

    u64 acc[4][16];
#pragma unroll
    for (int c = 0; c < 4; c++)
#pragma unroll
        for (int p = 0; p < 16; p++) acc[c][p] = 0ull;

    const float4* Wp = reinterpret_cast<const float4*>(W)
                     + (size_t)k0 * (DOUT / 4) + (n0 >> 2);

    // Front-batched prefetch buffer: 4 independent in-flight LDG.128
    float4 wbuf[KU];
#pragma unroll
    for (int u = 0; u < KU; u++)
        wbuf[u] = Wp[(size_t)u * (DOUT / 4)];

    for (int kc = 0; kc < KRANGE; kc += KC) {
        __syncthreads();
        {   // stage x chunk: KC*16 float2 = 1024 float4 (L2-resident)
            const float4* src = reinterpret_cast<const float4*>(
                g_xp + (size_t)(k0 + kc) * (MROWS / 2));
            float4* dst = reinterpret_cast<float4*>(xs);
#pragma unroll
            for (int i = 0; i < 8; i++)
                dst[tid + i * THREADS] = src[tid + i * THREADS];
        }
        __syncthreads();

#pragma unroll 1
        for (int kk = 0; kk < KC; kk += KU) {
            // consume current group into registers, then immediately issue
            // the next group's 4 LDGs (front-batched -> MLP=4)
            float4 wcur[KU];
#pragma unroll
            for (int u = 0; u < KU; u++) wcur[u] = wbuf[u];

            const int knext = kc + kk + KU;
            if (knext < KRANGE) {
#pragma unroll
                for (int u = 0; u < KU; u++)
                    wbuf[u] = Wp[(size_t)(knext + u) * (DOUT / 4)];
            }

#pragma unroll
            for (int u = 0; u < KU; u++) {
                float4 w = wcur[u];

                // ---- abs-argmax (signed value) over the 32-wide block ----
                float b = w.x;
                if (fabsf(w.y) > fabsf(b)) b = w.y;   // strict > keeps earliest index
                if (fabsf(w.z) > fabsf(b)) b = w.z;
                if (fabsf(w.w) > fabsf(b)) b = w.w;
#pragma unroll
                for (int off = 1; off <= 4; off <<= 1) {
                    float o  = __shfl_xor_sync(0xffffffffu, b, off);
                    float ab = fabsf(b), ao = fabsf(o);
                    bool keep = (ab > ao) || (ab == ao && (lane & off) == 0);
                    b = keep ? b : o;
                }

                // ---- Q4_0 scale (fp16 round-trip) + RN reciprocal ----
                float d     = b * -0.125f;                       // exact: /8
                float scale = __half2float(__float2half_rn(d));  // fp16 round-trip
                float inv   = __frcp_rn(d);                      // == RN(1/d) == 1.0/d
                float n8s   = scale * -8.0f;

                // ---- dequant 4 weights ----
                float wv[4] = {w.x, w.y, w.z, w.w};
                u64 wb[4];
#pragma unroll
                for (int c = 0; c < 4; c++) {
                    float t = fmaf(wv[c], inv, 8.5f);  // NaN if zero-block
                    t = truncf(t);
                    t = fminf(t, 15.0f);               // fminf(NaN,15)=15 -> scale(=0)*7=0
                    wb[c] = pack2(fmaf(scale, t, n8s)); // scale*(q-8), exact
                }

                // ---- 64 packed f32x2 FMAs: 4 cols x 16 m-pairs ----
                const u64* xk = reinterpret_cast<const u64*>(
                    xs + (kk + u) * (MROWS / 2));
#pragma unroll
                for (int p = 0; p < 16; p++) {
                    u64 xv = xk[p];                     // broadcast LDS.64
                    acc[0][p] = fma2(xv, wb[0], acc[0][p]);
                    acc[1][p] = fma2(xv, wb[1], acc[1][p]);
                    acc[2][p] = fma2(xv, wb[2], acc[2][p]);
                    acc[3][p] = fma2(xv, wb[3], acc[3][p]);
                }
            }
        }
    }

    // ---- write split-k partials (coalesced float4 rows) ----
    float* out = g_partial + (size_t)blockIdx.y * (MROWS * DOUT);
#pragma unroll
    for (int p = 0; p < 16; p++) {
        float lo0, hi0, lo1, hi1, lo2, hi2, lo3, hi3;
        unpack2(acc[0][p], lo0, hi0);
        unpack2(acc[1][p], lo1, hi1);
        unpack2(acc[2][p], lo2, hi2);
        unpack2(acc[3][p], lo3, hi3);
        *reinterpret_cast<float4*>(out + (size_t)(2 * p)     * DOUT + n0) =
            make_float4(lo0, lo1, lo2, lo3);
        *reinterpret_cast<float4*>(out + (size_t)(2 * p + 1) * DOUT + n0) =
            make_float4(hi0, hi1, hi2, hi3);
    }
}

// ---------------------------------------------------------------------------
// Epilog: out = bias + sum_k partials
// ---------------------------------------------------------------------------
__global__ void reduce_kernel(const float* __restrict__ bias, float* __restrict__ out) {
    int i = blockIdx.x * blockDim.x + threadIdx.x;   // float4 index
    if (i >= (MROWS * DOUT) / 4) return;
    int n4 = i & (DOUT / 4 - 1);
    float4 s = reinterpret_cast<const float4*>(bias)[n4];
#pragma unroll
    for (int ks = 0; ks < KSPLIT; ks++) {
        float4 p = reinterpret_cast<const float4*>(
            g_partial + (size_t)ks * MROWS * DOUT)[i];
        s.x += p.x; s.y += p.y; s.z += p.z; s.w += p.w;
    }
    reinterpret_cast<float4*>(out)[i] = s;
}

// ---------------------------------------------------------------------------
extern "C" void kernel_launch(void* const* d_in, const int* in_sizes, int n_in,
                              void* d_out, int out_size) {
    const float *X = nullptr, *W = nullptr, *B = nullptr;
    for (int i = 0; i < n_in; i++) {
        long long sz = in_sizes[i];
        if (sz == (long long)DIN * DOUT)      W = (const float*)d_in[i];
        else if (sz == (long long)MROWS*DIN)  X = (const float*)d_in[i];
        else if (sz == (long long)DOUT)       B = (const float*)d_in[i];
    }

    prep_x_kernel<<<DIN / 256, 256>>>(X);

    dim3 grid(DOUT / NTILE, KSPLIT);
    gemm_kernel<<<grid, THREADS>>>(W);

    reduce_kernel<<<(MROWS * DOUT / 4 + 255) / 256, 256>>>(B, (float*)d_out);
}

// round 6
// speedup vs baseline: 3.0271x; 1.5556x over previous
#include <cuda_runtime.h>
#include <cuda_fp16.h>
#include <cstdint>

#define DIN     8192
#define DOUT    8192
#define MR      32
#define KSPLIT  16
#define KRANGE  (DIN / KSPLIT)   // 512
#define KC      64               // k rows per chunk
#define NCHUNKS (KRANGE / KC)    // 8
#define NTILE   128              // n cols per CTA
#define GTHREADS 256

// padded smem row strides (u16 units) -> conflict-free ldmatrix
#define XSTR 72    // 64 k + 8 pad  (144 B)
#define WSTR 136   // 128 n + 8 pad (272 B)

// ---------------- static device scratch (no runtime alloc) ----------------
__device__ uint16_t g_xh[MR * DIN];                 // x hi bf16 [32][8192] (512KB)
__device__ uint16_t g_xl[MR * DIN];                 // x lo bf16
__device__ float    g_partial[KSPLIT * MR * DOUT];  // split-k partials (16MB)

// ---------------- helpers ----------------
__device__ __forceinline__ uint32_t smem_u32(const void* p) {
    uint32_t a;
    asm("{ .reg .u64 t; cvta.to.shared.u64 t, %1; cvt.u32.u64 %0, t; }" : "=r"(a) : "l"(p));
    return a;
}
// packed bf16x2: lo half = bf16(a), hi half = bf16(b)
__device__ __forceinline__ uint32_t bf16pack(float a, float b) {
    uint32_t r;
    asm("cvt.rn.bf16x2.f32 %0, %1, %2;" : "=r"(r) : "f"(b), "f"(a));
    return r;
}
__device__ __forceinline__ void ldsm4(uint32_t* r, uint32_t addr) {
    asm volatile("ldmatrix.sync.aligned.m8n8.x4.shared.b16 {%0,%1,%2,%3}, [%4];"
        : "=r"(r[0]), "=r"(r[1]), "=r"(r[2]), "=r"(r[3]) : "r"(addr));
}
__device__ __forceinline__ void ldsm4t(uint32_t* r, uint32_t addr) {
    asm volatile("ldmatrix.sync.aligned.m8n8.x4.trans.shared.b16 {%0,%1,%2,%3}, [%4];"
        : "=r"(r[0]), "=r"(r[1]), "=r"(r[2]), "=r"(r[3]) : "r"(addr));
}
__device__ __forceinline__ void mma_bf16(float* d, const uint32_t* a, const uint32_t* b) {
    asm volatile("mma.sync.aligned.m16n8k16.row.col.f32.bf16.bf16.f32 "
        "{%0,%1,%2,%3}, {%4,%5,%6,%7}, {%8,%9}, {%0,%1,%2,%3};"
        : "+f"(d[0]), "+f"(d[1]), "+f"(d[2]), "+f"(d[3])
        : "r"(a[0]), "r"(a[1]), "r"(a[2]), "r"(a[3]), "r"(b[0]), "r"(b[1]));
}

// ---------------------------------------------------------------------------
// Prep: split x fp32 [32][8192] -> bf16 hi + bf16 lo (row-major, same shape)
// ---------------------------------------------------------------------------
__global__ void prep_x_kernel(const float* __restrict__ x) {
    int idx = blockIdx.x * blockDim.x + threadIdx.x;   // float4 index, 65536 total
    float4 v = reinterpret_cast<const float4*>(x)[idx];
    uint32_t h01 = bf16pack(v.x, v.y);
    uint32_t h23 = bf16pack(v.z, v.w);
    float l0 = v.x - __uint_as_float(h01 << 16);
    float l1 = v.y - __uint_as_float(h01 & 0xffff0000u);
    float l2 = v.z - __uint_as_float(h23 << 16);
    float l3 = v.w - __uint_as_float(h23 & 0xffff0000u);
    uint32_t lo01 = bf16pack(l0, l1);
    uint32_t lo23 = bf16pack(l2, l3);
    reinterpret_cast<uint2*>(g_xh)[idx] = make_uint2(h01, h23);
    reinterpret_cast<uint2*>(g_xl)[idx] = make_uint2(lo01, lo23);
}

// ---------------------------------------------------------------------------
// Main: fused Q4_0 dequant -> bf16 hi/lo smem tiles -> mma.sync (HMMA).
// grid = (DOUT/NTILE, KSPLIT), 256 threads (8 warps).
// Per chunk (64k x 128n): warp wid dequants k-rows wid*8..wid*8+7 (lane owns
// 4 consecutive n; 8-lane shuffle amax per 32-n block), writes bf16 hi/lo to
// padded smem; then each warp computes its n16 slice with 3-term mma.sync
// (xh*wh + xh*wl + xl*wh, fp32 accum).
// ---------------------------------------------------------------------------
__global__ void __launch_bounds__(GTHREADS, 2)
gemm_kernel(const float* __restrict__ W) {
    __shared__ __align__(16) uint16_t sXH[MR * XSTR];   // 4.5 KB
    __shared__ __align__(16) uint16_t sXL[MR * XSTR];
    __shared__ __align__(16) uint16_t sWH[KC * WSTR];   // 17 KB
    __shared__ __align__(16) uint16_t sWL[KC * WSTR];

    const int tid  = threadIdx.x;
    const int wid  = tid >> 5;
    const int lane = tid & 31;
    const int n0   = blockIdx.x * NTILE;
    const int ks   = blockIdx.y;
    const int k0   = ks * KRANGE;

    const uint32_t xh_s = smem_u32(sXH);
    const uint32_t xl_s = smem_u32(sXL);
    const uint32_t wh_s = smem_u32(sWH);
    const uint32_t wl_s = smem_u32(sWL);

    // ldmatrix lane addressing components (row = lane&15, colgrp = lane>>4)
    const int lrow = lane & 15;
    const int lcol = lane >> 4;

    float d[2][2][4];   // [mtile][ntile][frag]
#pragma unroll
    for (int a = 0; a < 2; a++)
#pragma unroll
        for (int b = 0; b < 2; b++)
#pragma unroll
            for (int j = 0; j < 4; j++) d[a][b][j] = 0.0f;

    // front-batched W prefetch for chunk 0 (8 x LDG.128, MLP=8)
    float4 wv[8];
#pragma unroll
    for (int r = 0; r < 8; r++)
        wv[r] = reinterpret_cast<const float4*>(
            W + (size_t)(k0 + wid * 8 + r) * DOUT + n0)[lane];

    for (int c = 0; c < NCHUNKS; c++) {
        const int kb = k0 + c * KC;

        // ---- copy x chunk (pre-split bf16) into padded smem ----
        {
            const int m   = tid >> 3;    // 0..31
            const int seg = tid & 7;     // 0..7 (16B segments)
            const uint4* srch = reinterpret_cast<const uint4*>(g_xh) + (m * 1024 + (kb >> 3) + seg);
            const uint4* srcl = reinterpret_cast<const uint4*>(g_xl) + (m * 1024 + (kb >> 3) + seg);
            *reinterpret_cast<uint4*>(sXH + m * XSTR + seg * 8) = *srch;
            *reinterpret_cast<uint4*>(sXL + m * XSTR + seg * 8) = *srcl;
        }

        // ---- dequant 8 k-rows per warp -> bf16 hi/lo smem ----
#pragma unroll
        for (int r = 0; r < 8; r++) {
            float4 w = wv[r];

            // abs-argmax (signed value) over the 32-wide n block (8 lanes)
            float b = w.x;
            if (fabsf(w.y) > fabsf(b)) b = w.y;
            if (fabsf(w.z) > fabsf(b)) b = w.z;
            if (fabsf(w.w) > fabsf(b)) b = w.w;
#pragma unroll
            for (int off = 1; off <= 4; off <<= 1) {
                float o  = __shfl_xor_sync(0xffffffffu, b, off);
                float ab = fabsf(b), ao = fabsf(o);
                bool keep = (ab > ao) || (ab == ao && (lane & off) == 0);
                b = keep ? b : o;
            }
            float dd    = b * -0.125f;                       // exact /8
            float scale = __half2float(__float2half_rn(dd)); // fp16 round-trip
            float inv   = __frcp_rn(dd);                     // == RN(1/dd)
            float n8s   = scale * -8.0f;

            float t0 = fminf(truncf(fmaf(w.x, inv, 8.5f)), 15.0f);
            float t1 = fminf(truncf(fmaf(w.y, inv, 8.5f)), 15.0f);
            float t2 = fminf(truncf(fmaf(w.z, inv, 8.5f)), 15.0f);
            float t3 = fminf(truncf(fmaf(w.w, inv, 8.5f)), 15.0f);
            float q0 = fmaf(scale, t0, n8s);
            float q1 = fmaf(scale, t1, n8s);
            float q2 = fmaf(scale, t2, n8s);
            float q3 = fmaf(scale, t3, n8s);

            uint32_t h01 = bf16pack(q0, q1);
            uint32_t h23 = bf16pack(q2, q3);
            float l0 = q0 - __uint_as_float(h01 << 16);
            float l1 = q1 - __uint_as_float(h01 & 0xffff0000u);
            float l2 = q2 - __uint_as_float(h23 << 16);
            float l3 = q3 - __uint_as_float(h23 & 0xffff0000u);
            uint32_t lo01 = bf16pack(l0, l1);
            uint32_t lo23 = bf16pack(l2, l3);

            const int kr = wid * 8 + r;
            uint32_t ha = wh_s + (uint32_t)(kr * WSTR + lane * 4) * 2;
            uint32_t la = wl_s + (uint32_t)(kr * WSTR + lane * 4) * 2;
            asm volatile("st.shared.v2.b32 [%0], {%1,%2};" :: "r"(ha), "r"(h01), "r"(h23) : "memory");
            asm volatile("st.shared.v2.b32 [%0], {%1,%2};" :: "r"(la), "r"(lo01), "r"(lo23) : "memory");
        }

        // ---- prefetch next chunk's W (hidden behind mma + barriers) ----
        if (c + 1 < NCHUNKS) {
            const int kb2 = kb + KC;
#pragma unroll
            for (int r = 0; r < 8; r++)
                wv[r] = reinterpret_cast<const float4*>(
                    W + (size_t)(kb2 + wid * 8 + r) * DOUT + n0)[lane];
        }

        __syncthreads();

        // ---- mma: warp owns n slice [wid*16, wid*16+16) ----
#pragma unroll
        for (int ksi = 0; ksi < 4; ksi++) {
            uint32_t ah0[4], ah1[4], al0[4], al1[4], bh[4], bl[4];
            uint32_t arow = (uint32_t)(lrow * XSTR + ksi * 16 + lcol * 8) * 2;
            ldsm4(ah0, xh_s + arow);                       // m 0..15
            ldsm4(ah1, xh_s + arow + 16u * XSTR * 2);      // m 16..31
            ldsm4(al0, xl_s + arow);
            ldsm4(al1, xl_s + arow + 16u * XSTR * 2);

            uint32_t brow = (uint32_t)((ksi * 16 + lrow) * WSTR + wid * 16 + lcol * 8) * 2;
            ldsm4t(bh, wh_s + brow);
            ldsm4t(bl, wl_s + brow);

            // 3 precision terms, 2 m-tiles x 2 n-tiles
            mma_bf16(d[0][0], ah0, bh);     mma_bf16(d[0][1], ah0, bh + 2);
            mma_bf16(d[1][0], ah1, bh);     mma_bf16(d[1][1], ah1, bh + 2);
            mma_bf16(d[0][0], ah0, bl);     mma_bf16(d[0][1], ah0, bl + 2);
            mma_bf16(d[1][0], ah1, bl);     mma_bf16(d[1][1], ah1, bl + 2);
            mma_bf16(d[0][0], al0, bh);     mma_bf16(d[0][1], al0, bh + 2);
            mma_bf16(d[1][0], al1, bh);     mma_bf16(d[1][1], al1, bh + 2);
        }
        __syncthreads();
    }

    // ---- write split-k partials ----
    {
        const int g4   = lane >> 2;          // 0..7
        const int tid4 = lane & 3;           // 0..3
        float* base = g_partial + (size_t)ks * MR * DOUT + n0 + wid * 16;
#pragma unroll
        for (int mt = 0; mt < 2; mt++) {
#pragma unroll
            for (int nt = 0; nt < 2; nt++) {
                int col = nt * 8 + tid4 * 2;
                float* p0 = base + (size_t)(mt * 16 + g4)     * DOUT + col;
                float* p1 = base + (size_t)(mt * 16 + g4 + 8) * DOUT + col;
                *reinterpret_cast<float2*>(p0) = make_float2(d[mt][nt][0], d[mt][nt][1]);
                *reinterpret_cast<float2*>(p1) = make_float2(d[mt][nt][2], d[mt][nt][3]);
            }
        }
    }
}

// ---------------------------------------------------------------------------
// Epilog: out = bias + sum_ks partials
// ---------------------------------------------------------------------------
__global__ void reduce_kernel(const float* __restrict__ bias, float* __restrict__ out) {
    int i = blockIdx.x * blockDim.x + threadIdx.x;   // float4 index
    if (i >= (MR * DOUT) / 4) return;
    int n4 = i & (DOUT / 4 - 1);
    float4 s = reinterpret_cast<const float4*>(bias)[n4];
#pragma unroll
    for (int k = 0; k < KSPLIT; k++) {
        float4 p = reinterpret_cast<const float4*>(g_partial + (size_t)k * MR * DOUT)[i];
        s.x += p.x; s.y += p.y; s.z += p.z; s.w += p.w;
    }
    reinterpret_cast<float4*>(out)[i] = s;
}

// ---------------------------------------------------------------------------
extern "C" void kernel_launch(void* const* d_in, const int* in_sizes, int n_in,
                              void* d_out, int out_size) {
    const float *X = nullptr, *W = nullptr, *B = nullptr;
    for (int i = 0; i < n_in; i++) {
        long long sz = in_sizes[i];
        if      (sz == (long long)DIN * DOUT) W = (const float*)d_in[i];
        else if (sz == (long long)MR * DIN)   X = (const float*)d_in[i];
        else if (sz == (long long)DOUT)       B = (const float*)d_in[i];
    }

    prep_x_kernel<<<(MR * DIN / 4) / 256, 256>>>(X);

    dim3 grid(DOUT / NTILE, KSPLIT);   // 64 x 16 = 1024 CTAs
    gemm_kernel<<<grid, GTHREADS>>>(W);

    reduce_kernel<<<(MR * DOUT / 4 + 255) / 256, 256>>>(B, (float*)d_out);
}